// round 4
// baseline (speedup 1.0000x reference)
#include <cuda_runtime.h>

#define N_NODES 50000
#define E_EDGES 1600000
#define IN_C    128
#define HID     64
#define OUT_C   64
#define EPS     1e-5f
#define NEG_SLOPE 0.01f

// Scratch (allocation-free rule: __device__ globals)
__device__ float g_h[N_NODES * HID];    // 12.8 MB
__device__ float g_agg[N_NODES * HID];  // 12.8 MB

// ---------------------------------------------------------------------------
// Kernel A: h = LayerNorm(LeakyReLU(x @ W1^T + b1)) ; one warp per row.
// ---------------------------------------------------------------------------
__global__ void mlp_ln_kernel(const float* __restrict__ x,
                              const float* __restrict__ W1,
                              const float* __restrict__ b1,
                              const float* __restrict__ gamma,
                              const float* __restrict__ beta) {
    __shared__ float sW[IN_C][HID + 1];   // [k][j], padded -> conflict-free
    __shared__ float sb[HID], sg[HID], sbt[HID];

    for (int idx = threadIdx.x; idx < HID * IN_C; idx += blockDim.x) {
        int j = idx / IN_C, k = idx % IN_C;
        sW[k][j] = W1[idx];
    }
    if (threadIdx.x < HID) {
        sb[threadIdx.x]  = b1[threadIdx.x];
        sg[threadIdx.x]  = gamma[threadIdx.x];
        sbt[threadIdx.x] = beta[threadIdx.x];
    }
    __syncthreads();

    const int warp = threadIdx.x >> 5, lane = threadIdx.x & 31;
    const int nwarps = blockDim.x >> 5;

    for (int row = blockIdx.x * nwarps + warp; row < N_NODES;
         row += gridDim.x * nwarps) {
        const float* xr = x + (size_t)row * IN_C;
        float xv0 = xr[lane], xv1 = xr[lane + 32],
              xv2 = xr[lane + 64], xv3 = xr[lane + 96];

        float acc0 = sb[lane], acc1 = sb[lane + 32];

        #pragma unroll
        for (int l = 0; l < 32; l++) {
            float a = __shfl_sync(0xffffffffu, xv0, l);
            acc0 += a * sW[l][lane];
            acc1 += a * sW[l][lane + 32];
        }
        #pragma unroll
        for (int l = 0; l < 32; l++) {
            float a = __shfl_sync(0xffffffffu, xv1, l);
            acc0 += a * sW[32 + l][lane];
            acc1 += a * sW[32 + l][lane + 32];
        }
        #pragma unroll
        for (int l = 0; l < 32; l++) {
            float a = __shfl_sync(0xffffffffu, xv2, l);
            acc0 += a * sW[64 + l][lane];
            acc1 += a * sW[64 + l][lane + 32];
        }
        #pragma unroll
        for (int l = 0; l < 32; l++) {
            float a = __shfl_sync(0xffffffffu, xv3, l);
            acc0 += a * sW[96 + l][lane];
            acc1 += a * sW[96 + l][lane + 32];
        }

        // LeakyReLU
        acc0 = acc0 > 0.f ? acc0 : acc0 * NEG_SLOPE;
        acc1 = acc1 > 0.f ? acc1 : acc1 * NEG_SLOPE;

        // LayerNorm over the 64 hidden values
        float s  = acc0 + acc1;
        float s2 = acc0 * acc0 + acc1 * acc1;
        #pragma unroll
        for (int off = 16; off > 0; off >>= 1) {
            s  += __shfl_xor_sync(0xffffffffu, s,  off);
            s2 += __shfl_xor_sync(0xffffffffu, s2, off);
        }
        float mu   = s * (1.f / HID);
        float var  = s2 * (1.f / HID) - mu * mu;
        float rstd = rsqrtf(var + EPS);

        float* hr = g_h + (size_t)row * HID;
        hr[lane]      = (acc0 - mu) * rstd * sg[lane]      + sbt[lane];
        hr[lane + 32] = (acc1 - mu) * rstd * sg[lane + 32] + sbt[lane + 32];
    }
}

// ---------------------------------------------------------------------------
// Kernel B: agg = +inf
// ---------------------------------------------------------------------------
__global__ void init_agg_kernel() {
    int i = blockIdx.x * blockDim.x + threadIdx.x;
    if (i < N_NODES * HID) g_agg[i] = __int_as_float(0x7f800000);
}

// ---------------------------------------------------------------------------
// Kernel C: scatter-min. One warp per edge; 2 channels per lane.
// Stale-read filter: plain load of agg >= true current value (monotone
// decreasing), so skipping when v >= loaded is always safe.
// Float atomic-min via signed-min (v>=0) / unsigned-max (v<0) bit trick.
// ---------------------------------------------------------------------------
__device__ __forceinline__ void atomicMinF(float* addr, float v) {
    if (v >= 0.f) atomicMin((int*)addr, __float_as_int(v));
    else          atomicMax((unsigned int*)addr, __float_as_uint(v));
}

__global__ void scatter_min_kernel(const int* __restrict__ ei) {
    int idx = blockIdx.x * blockDim.x + threadIdx.x;
    int e = idx >> 5;
    int lane = idx & 31;
    if (e >= E_EDGES) return;
    int src = ei[e];             // edge_index[0, e]  (int32!)
    int dst = ei[E_EDGES + e];   // edge_index[1, e]
    const float* hs = g_h   + (size_t)src * HID;
    float*       ag = g_agg + (size_t)dst * HID;
    float v0 = hs[lane], v1 = hs[lane + 32];
    float c0 = ag[lane], c1 = ag[lane + 32];   // stale-read filter
    if (v0 < c0) atomicMinF(ag + lane,      v0);
    if (v1 < c1) atomicMinF(ag + lane + 32, v1);
}

// ---------------------------------------------------------------------------
// Kernel D: out = where(isinf(agg), 0, agg) @ W2^T + b2 ; warp per row.
// ---------------------------------------------------------------------------
__global__ void out_kernel(const float* __restrict__ W2,
                           const float* __restrict__ b2,
                           float* __restrict__ out) {
    __shared__ float sW[HID][OUT_C + 1];  // [k][j]
    __shared__ float sb[OUT_C];

    for (int idx = threadIdx.x; idx < OUT_C * HID; idx += blockDim.x) {
        int j = idx / HID, k = idx % HID;
        sW[k][j] = W2[idx];
    }
    if (threadIdx.x < OUT_C) sb[threadIdx.x] = b2[threadIdx.x];
    __syncthreads();

    const int warp = threadIdx.x >> 5, lane = threadIdx.x & 31;
    const int nwarps = blockDim.x >> 5;
    const float inf = __int_as_float(0x7f800000);

    for (int row = blockIdx.x * nwarps + warp; row < N_NODES;
         row += gridDim.x * nwarps) {
        const float* ar = g_agg + (size_t)row * HID;
        float a0 = ar[lane], a1 = ar[lane + 32];
        if (a0 == inf) a0 = 0.f;
        if (a1 == inf) a1 = 0.f;

        float acc0 = sb[lane], acc1 = sb[lane + 32];
        #pragma unroll
        for (int l = 0; l < 32; l++) {
            float k0 = __shfl_sync(0xffffffffu, a0, l);
            float k1 = __shfl_sync(0xffffffffu, a1, l);
            acc0 += k0 * sW[l][lane]      + k1 * sW[32 + l][lane];
            acc1 += k0 * sW[l][lane + 32] + k1 * sW[32 + l][lane + 32];
        }
        float* orow = out + (size_t)row * OUT_C;
        orow[lane]      = acc0;
        orow[lane + 32] = acc1;
    }
}

// ---------------------------------------------------------------------------
// Launch
// Inputs (metadata order): 0:x 1:x_e 2:edge_index(int32 — JAX x64 disabled!)
//                          3:W1 4:b1 5:gamma 6:beta 7:W2 8:b2
// ---------------------------------------------------------------------------
extern "C" void kernel_launch(void* const* d_in, const int* in_sizes, int n_in,
                              void* d_out, int out_size) {
    const float* x     = (const float*)d_in[0];
    const int*   ei    = (const int*)d_in[2];
    const float* W1    = (const float*)d_in[3];
    const float* b1    = (const float*)d_in[4];
    const float* gamma = (const float*)d_in[5];
    const float* beta  = (const float*)d_in[6];
    const float* W2    = (const float*)d_in[7];
    const float* b2    = (const float*)d_in[8];
    float*       out   = (float*)d_out;

    // A: fused MLP + LayerNorm
    mlp_ln_kernel<<<592, 256>>>(x, W1, b1, gamma, beta);

    // B: init agg to +inf
    init_agg_kernel<<<(N_NODES * HID + 255) / 256, 256>>>();

    // C: scatter-min over edges (warp per edge, filtered atomics)
    {
        long long total_threads = (long long)E_EDGES * 32;
        int blocks = (int)((total_threads + 255) / 256);
        scatter_min_kernel<<<blocks, 256>>>(ei);
    }

    // D: output linear with inf->0 fixup
    out_kernel<<<592, 256>>>(W2, b2, out);
}

// round 5
// speedup vs baseline: 1.5057x; 1.5057x over previous
#include <cuda_runtime.h>

#define N_NODES 50000
#define E_EDGES 1600000
#define IN_C    128
#define HID     64
#define OUT_C   64
#define EPS     1e-5f
#define NEG_SLOPE 0.01f

// Scratch (allocation-free rule: __device__ globals)
__device__ float g_h[N_NODES * HID];    // 12.8 MB
__device__ float g_agg[N_NODES * HID];  // 12.8 MB

// ---------------------------------------------------------------------------
// Kernel A: h = LayerNorm(LeakyReLU(x @ W1^T + b1))
// One warp per 4 rows: weight LDS amortized 4x; x broadcast via shfl.
// ---------------------------------------------------------------------------
__global__ void mlp_ln_kernel(const float* __restrict__ x,
                              const float* __restrict__ W1,
                              const float* __restrict__ b1,
                              const float* __restrict__ gamma,
                              const float* __restrict__ beta) {
    __shared__ float sW[IN_C][HID + 1];   // [k][j], padded
    __shared__ float sb[HID], sg[HID], sbt[HID];

    for (int idx = threadIdx.x; idx < HID * IN_C; idx += blockDim.x) {
        int j = idx / IN_C, k = idx % IN_C;
        sW[k][j] = W1[idx];
    }
    if (threadIdx.x < HID) {
        sb[threadIdx.x]  = b1[threadIdx.x];
        sg[threadIdx.x]  = gamma[threadIdx.x];
        sbt[threadIdx.x] = beta[threadIdx.x];
    }
    __syncthreads();

    const int warp = threadIdx.x >> 5, lane = threadIdx.x & 31;
    const int nwarps = blockDim.x >> 5;
    const int NTILES = N_NODES / 4;   // 12500, exact

    for (int tile = blockIdx.x * nwarps + warp; tile < NTILES;
         tile += gridDim.x * nwarps) {
        const int row = tile * 4;

        float xv[4][4];
        #pragma unroll
        for (int r = 0; r < 4; r++) {
            const float* xr = x + (size_t)(row + r) * IN_C;
            xv[r][0] = xr[lane];
            xv[r][1] = xr[lane + 32];
            xv[r][2] = xr[lane + 64];
            xv[r][3] = xr[lane + 96];
        }

        float acc0[4], acc1[4];
        #pragma unroll
        for (int r = 0; r < 4; r++) { acc0[r] = sb[lane]; acc1[r] = sb[lane + 32]; }

        #pragma unroll
        for (int c = 0; c < 4; c++) {
            #pragma unroll
            for (int l = 0; l < 32; l++) {
                float w0 = sW[c * 32 + l][lane];
                float w1 = sW[c * 32 + l][lane + 32];
                #pragma unroll
                for (int r = 0; r < 4; r++) {
                    float a = __shfl_sync(0xffffffffu, xv[r][c], l);
                    acc0[r] += a * w0;
                    acc1[r] += a * w1;
                }
            }
        }

        #pragma unroll
        for (int r = 0; r < 4; r++) {
            float a0 = acc0[r], a1 = acc1[r];
            // LeakyReLU
            a0 = a0 > 0.f ? a0 : a0 * NEG_SLOPE;
            a1 = a1 > 0.f ? a1 : a1 * NEG_SLOPE;
            // LayerNorm over 64 values
            float s  = a0 + a1;
            float s2 = a0 * a0 + a1 * a1;
            #pragma unroll
            for (int off = 16; off > 0; off >>= 1) {
                s  += __shfl_xor_sync(0xffffffffu, s,  off);
                s2 += __shfl_xor_sync(0xffffffffu, s2, off);
            }
            float mu   = s * (1.f / HID);
            float var  = s2 * (1.f / HID) - mu * mu;
            float rstd = rsqrtf(var + EPS);

            float* hr = g_h + (size_t)(row + r) * HID;
            hr[lane]      = (a0 - mu) * rstd * sg[lane]      + sbt[lane];
            hr[lane + 32] = (a1 - mu) * rstd * sg[lane + 32] + sbt[lane + 32];
        }
    }
}

// ---------------------------------------------------------------------------
// Kernel B: agg = +inf (vectorized)
// ---------------------------------------------------------------------------
__global__ void init_agg_kernel() {
    int i = blockIdx.x * blockDim.x + threadIdx.x;
    const float inf = __int_as_float(0x7f800000);
    float4 v = make_float4(inf, inf, inf, inf);
    if (i < N_NODES * HID / 4) reinterpret_cast<float4*>(g_agg)[i] = v;
}

// ---------------------------------------------------------------------------
// Kernel C: scatter-min. Half-warp (16 lanes) per edge, float4 per lane.
// Stale-read filter: plain load of agg >= true current value (monotone
// decreasing), so skipping when v >= loaded is always safe.
// ---------------------------------------------------------------------------
__device__ __forceinline__ void atomicMinF(float* addr, float v) {
    if (v >= 0.f) atomicMin((int*)addr, __float_as_int(v));
    else          atomicMax((unsigned int*)addr, __float_as_uint(v));
}

__global__ void scatter_min_kernel(const int* __restrict__ ei) {
    int idx = blockIdx.x * blockDim.x + threadIdx.x;
    int e = idx >> 4;            // 16 lanes per edge
    int c = idx & 15;            // float4 chunk index (HID/4 = 16)
    if (e >= E_EDGES) return;
    int src = ei[e];             // int32 edge_index
    int dst = ei[E_EDGES + e];

    const float4* hs = reinterpret_cast<const float4*>(g_h   + (size_t)src * HID);
    float4*       ag = reinterpret_cast<float4*>(g_agg + (size_t)dst * HID);

    float4 v   = hs[c];
    float4 cur = ag[c];          // stale-read filter (safe: monotone min)
    float* a = reinterpret_cast<float*>(ag + c);
    if (v.x < cur.x) atomicMinF(a + 0, v.x);
    if (v.y < cur.y) atomicMinF(a + 1, v.y);
    if (v.z < cur.z) atomicMinF(a + 2, v.z);
    if (v.w < cur.w) atomicMinF(a + 3, v.w);
}

// ---------------------------------------------------------------------------
// Kernel D: out = where(isinf(agg), 0, agg) @ W2^T + b2
// One warp per 4 rows: weight LDS amortized 4x.
// ---------------------------------------------------------------------------
__global__ void out_kernel(const float* __restrict__ W2,
                           const float* __restrict__ b2,
                           float* __restrict__ out) {
    __shared__ float sW[HID][OUT_C + 1];  // [k][j]
    __shared__ float sb[OUT_C];

    for (int idx = threadIdx.x; idx < OUT_C * HID; idx += blockDim.x) {
        int j = idx / HID, k = idx % HID;
        sW[k][j] = W2[idx];
    }
    if (threadIdx.x < OUT_C) sb[threadIdx.x] = b2[threadIdx.x];
    __syncthreads();

    const int warp = threadIdx.x >> 5, lane = threadIdx.x & 31;
    const int nwarps = blockDim.x >> 5;
    const float inf = __int_as_float(0x7f800000);
    const int NTILES = N_NODES / 4;   // 12500, exact

    for (int tile = blockIdx.x * nwarps + warp; tile < NTILES;
         tile += gridDim.x * nwarps) {
        const int row = tile * 4;

        float a0[4], a1[4], acc0[4], acc1[4];
        #pragma unroll
        for (int r = 0; r < 4; r++) {
            const float* ar = g_agg + (size_t)(row + r) * HID;
            float v0 = ar[lane], v1 = ar[lane + 32];
            a0[r] = (v0 == inf) ? 0.f : v0;
            a1[r] = (v1 == inf) ? 0.f : v1;
            acc0[r] = sb[lane];
            acc1[r] = sb[lane + 32];
        }

        #pragma unroll
        for (int l = 0; l < 32; l++) {
            float w00 = sW[l][lane],      w01 = sW[l][lane + 32];
            float w10 = sW[32 + l][lane], w11 = sW[32 + l][lane + 32];
            #pragma unroll
            for (int r = 0; r < 4; r++) {
                float k0 = __shfl_sync(0xffffffffu, a0[r], l);
                float k1 = __shfl_sync(0xffffffffu, a1[r], l);
                acc0[r] += k0 * w00 + k1 * w10;
                acc1[r] += k0 * w01 + k1 * w11;
            }
        }

        #pragma unroll
        for (int r = 0; r < 4; r++) {
            float* orow = out + (size_t)(row + r) * OUT_C;
            orow[lane]      = acc0[r];
            orow[lane + 32] = acc1[r];
        }
    }
}

// ---------------------------------------------------------------------------
// Launch
// Inputs: 0:x 1:x_e 2:edge_index(int32) 3:W1 4:b1 5:gamma 6:beta 7:W2 8:b2
// ---------------------------------------------------------------------------
extern "C" void kernel_launch(void* const* d_in, const int* in_sizes, int n_in,
                              void* d_out, int out_size) {
    const float* x     = (const float*)d_in[0];
    const int*   ei    = (const int*)d_in[2];
    const float* W1    = (const float*)d_in[3];
    const float* b1    = (const float*)d_in[4];
    const float* gamma = (const float*)d_in[5];
    const float* beta  = (const float*)d_in[6];
    const float* W2    = (const float*)d_in[7];
    const float* b2    = (const float*)d_in[8];
    float*       out   = (float*)d_out;

    // A: fused MLP + LayerNorm (4 rows per warp)
    mlp_ln_kernel<<<1563, 256>>>(x, W1, b1, gamma, beta);

    // B: init agg to +inf
    init_agg_kernel<<<(N_NODES * HID / 4 + 255) / 256, 256>>>();

    // C: scatter-min (half-warp per edge, float4, filtered atomics)
    {
        long long total_threads = (long long)E_EDGES * 16;
        int blocks = (int)((total_threads + 255) / 256);
        scatter_min_kernel<<<blocks, 256>>>(ei);
    }

    // D: output linear with inf->0 fixup (4 rows per warp)
    out_kernel<<<1563, 256>>>(W2, b2, out);
}

// round 7
// speedup vs baseline: 1.9218x; 1.2764x over previous
#include <cuda_runtime.h>

#define N_NODES 50000
#define E_EDGES 1600000
#define IN_C    128
#define HID     64
#define OUT_C   64
#define EPS     1e-5f
#define NEG_SLOPE 0.01f

// Scratch (allocation-free rule: __device__ globals)
__device__ float g_h[N_NODES * HID];     // 12.8 MB  LayerNorm output
__device__ int   g_srcs[E_EDGES];        // 6.4 MB   CSR src lists (by dst)
__device__ int   g_deg[N_NODES];
__device__ int   g_off[N_NODES];
__device__ int   g_cur[N_NODES];
__device__ int   g_bsum[64];

// ---------------------------------------------------------------------------
// Kernel 1: h = LayerNorm(LeakyReLU(x @ W1^T + b1)); also zeroes g_deg.
// 4 rows per warp. W1 staged as float4 [k/4][j] (conflict-free LDS.128);
// x rows staged in warp-private shared, read back as broadcast float4.
// Inner step: 6 LDS.128 per 32 FMA -> FFMA-bound.
// ---------------------------------------------------------------------------
#define MLP_WARPS 4
__global__ void mlp_ln_kernel(const float* __restrict__ x,
                              const float* __restrict__ W1,
                              const float* __restrict__ b1,
                              const float* __restrict__ gamma,
                              const float* __restrict__ beta) {
    __shared__ float4 sW4[32 * 64];               // 32 KB: [kc][j]
    __shared__ float4 sX4[MLP_WARPS][4][32];      //  8 KB: warp-private x rows
    __shared__ float  sb[HID], sg[HID], sbt[HID];

    for (int idx = threadIdx.x; idx < HID * IN_C; idx += blockDim.x) {
        int j = idx / IN_C, k = idx % IN_C;
        ((float*)sW4)[(k >> 2) * 256 + j * 4 + (k & 3)] = W1[idx];
    }
    if (threadIdx.x < HID) {
        sb[threadIdx.x]  = b1[threadIdx.x];
        sg[threadIdx.x]  = gamma[threadIdx.x];
        sbt[threadIdx.x] = beta[threadIdx.x];
    }
    // zero degree histogram (next kernel fills it)
    int gt = blockIdx.x * blockDim.x + threadIdx.x;
    if (gt < N_NODES) g_deg[gt] = 0;
    __syncthreads();

    const int warp = threadIdx.x >> 5, lane = threadIdx.x & 31;
    const int NTILES = N_NODES / 4;   // 12500, exact

    for (int tile = blockIdx.x * MLP_WARPS + warp; tile < NTILES;
         tile += gridDim.x * MLP_WARPS) {
        const int row = tile * 4;
        float* sX = (float*)sX4[warp];
        #pragma unroll
        for (int r = 0; r < 4; r++) {
            const float* xr = x + (size_t)(row + r) * IN_C;
            sX[r * IN_C + lane]      = xr[lane];
            sX[r * IN_C + lane + 32] = xr[lane + 32];
            sX[r * IN_C + lane + 64] = xr[lane + 64];
            sX[r * IN_C + lane + 96] = xr[lane + 96];
        }
        __syncwarp();

        float acc0[4], acc1[4];
        #pragma unroll
        for (int r = 0; r < 4; r++) { acc0[r] = sb[lane]; acc1[r] = sb[lane + 32]; }

        #pragma unroll
        for (int kc = 0; kc < 32; kc++) {
            float4 w0 = sW4[kc * 64 + lane];
            float4 w1 = sW4[kc * 64 + lane + 32];
            #pragma unroll
            for (int r = 0; r < 4; r++) {
                float4 a = sX4[warp][r][kc];
                acc0[r] += a.x * w0.x + a.y * w0.y + a.z * w0.z + a.w * w0.w;
                acc1[r] += a.x * w1.x + a.y * w1.y + a.z * w1.z + a.w * w1.w;
            }
        }
        __syncwarp();   // before next tile overwrites sX

        #pragma unroll
        for (int r = 0; r < 4; r++) {
            float a0 = acc0[r], a1 = acc1[r];
            a0 = a0 > 0.f ? a0 : a0 * NEG_SLOPE;
            a1 = a1 > 0.f ? a1 : a1 * NEG_SLOPE;
            float s  = a0 + a1;
            float s2 = a0 * a0 + a1 * a1;
            #pragma unroll
            for (int off = 16; off > 0; off >>= 1) {
                s  += __shfl_xor_sync(0xffffffffu, s,  off);
                s2 += __shfl_xor_sync(0xffffffffu, s2, off);
            }
            float mu   = s * (1.f / HID);
            float var  = s2 * (1.f / HID) - mu * mu;
            float rstd = rsqrtf(var + EPS);

            float* hr = g_h + (size_t)(row + r) * HID;
            hr[lane]      = (a0 - mu) * rstd * sg[lane]      + sbt[lane];
            hr[lane + 32] = (a1 - mu) * rstd * sg[lane + 32] + sbt[lane + 32];
        }
    }
}

// ---------------------------------------------------------------------------
// CSR build: histogram -> 3-step exclusive scan -> bucket fill
// ---------------------------------------------------------------------------
__global__ void hist_kernel(const int* __restrict__ ei) {
    int e = blockIdx.x * blockDim.x + threadIdx.x;
    if (e < E_EDGES) atomicAdd(&g_deg[ei[E_EDGES + e]], 1);
}

__global__ void scan1_kernel() {   // 49 blocks x 1024: per-block exclusive scan
    __shared__ int s[1024];
    int tid = threadIdx.x;
    int gid = blockIdx.x * 1024 + tid;
    int v = (gid < N_NODES) ? g_deg[gid] : 0;
    s[tid] = v; __syncthreads();
    #pragma unroll
    for (int off = 1; off < 1024; off <<= 1) {
        int t = (tid >= off) ? s[tid - off] : 0;
        __syncthreads();
        s[tid] += t;
        __syncthreads();
    }
    if (gid < N_NODES) g_off[gid] = s[tid] - v;   // exclusive
    if (tid == 1023) g_bsum[blockIdx.x] = s[1023];
}

__global__ void scan2_kernel() {   // 1 block x 64: scan block sums
    __shared__ int s[64];
    int tid = threadIdx.x;
    int v = (tid < 49) ? g_bsum[tid] : 0;
    s[tid] = v; __syncthreads();
    #pragma unroll
    for (int off = 1; off < 64; off <<= 1) {
        int t = (tid >= off) ? s[tid - off] : 0;
        __syncthreads();
        s[tid] += t;
        __syncthreads();
    }
    g_bsum[tid] = s[tid] - v;       // exclusive
}

__global__ void scan3_kernel() {   // add block offsets; init cursors
    int i = blockIdx.x * blockDim.x + threadIdx.x;
    if (i < N_NODES) {
        int o = g_off[i] + g_bsum[i >> 10];
        g_off[i] = o;
        g_cur[i] = o;
    }
}

__global__ void fill_kernel(const int* __restrict__ ei) {
    int e = blockIdx.x * blockDim.x + threadIdx.x;
    if (e < E_EDGES) {
        int src = ei[e];
        int dst = ei[E_EDGES + e];
        int p = atomicAdd(&g_cur[dst], 1);
        g_srcs[p] = src;   // order nondeterministic; min is order-independent
    }
}

// ---------------------------------------------------------------------------
// Kernel 7: fused gather-min + output GEMM.
// One warp per dst node: min over its CSR src list (coalesced 256B row reads,
// atomic-free), deg==0 -> 0, then out[dst] = agg @ W2^T + b2 using the same
// float4 shared-staged scheme. g_agg eliminated entirely.
// ---------------------------------------------------------------------------
#define GO_WARPS 8
__global__ void gather_out_kernel(const float* __restrict__ W2,
                                  const float* __restrict__ b2,
                                  float* __restrict__ out) {
    __shared__ float4 sW4[16 * 64];          // 16 KB: [kc][j]
    __shared__ float4 sA4[GO_WARPS][16];     //  2 KB: warp-private agg row
    __shared__ float  sb[OUT_C];

    for (int idx = threadIdx.x; idx < OUT_C * HID; idx += blockDim.x) {
        int j = idx / HID, k = idx % HID;
        ((float*)sW4)[(k >> 2) * 256 + j * 4 + (k & 3)] = W2[idx];
    }
    if (threadIdx.x < OUT_C) sb[threadIdx.x] = b2[threadIdx.x];
    __syncthreads();

    const int warp = threadIdx.x >> 5, lane = threadIdx.x & 31;
    const float inf = __int_as_float(0x7f800000);

    for (int dst = blockIdx.x * GO_WARPS + warp; dst < N_NODES;
         dst += gridDim.x * GO_WARPS) {
        const int start = g_off[dst];
        const int deg   = g_deg[dst];

        float m0 = inf, m1 = inf;
        for (int base = 0; base < deg; base += 32) {
            int cnt = min(32, deg - base);
            int sid = (lane < cnt) ? g_srcs[start + base + lane] : 0;
            for (int j = 0; j < cnt; j++) {
                int s = __shfl_sync(0xffffffffu, sid, j);
                const float* hs = g_h + (size_t)s * HID;
                m0 = fminf(m0, hs[lane]);
                m1 = fminf(m1, hs[lane + 32]);
            }
        }
        if (deg == 0) { m0 = 0.f; m1 = 0.f; }   // PyG fill for isolated nodes

        float* sA = (float*)sA4[warp];
        sA[lane]      = m0;
        sA[lane + 32] = m1;
        __syncwarp();

        float acc0 = sb[lane], acc1 = sb[lane + 32];
        #pragma unroll
        for (int kc = 0; kc < 16; kc++) {
            float4 a  = sA4[warp][kc];
            float4 w0 = sW4[kc * 64 + lane];
            float4 w1 = sW4[kc * 64 + lane + 32];
            acc0 += a.x * w0.x + a.y * w0.y + a.z * w0.z + a.w * w0.w;
            acc1 += a.x * w1.x + a.y * w1.y + a.z * w1.z + a.w * w1.w;
        }
        __syncwarp();

        float* orow = out + (size_t)dst * OUT_C;
        orow[lane]      = acc0;
        orow[lane + 32] = acc1;
    }
}

// ---------------------------------------------------------------------------
// Launch
// Inputs: 0:x 1:x_e 2:edge_index(int32) 3:W1 4:b1 5:gamma 6:beta 7:W2 8:b2
// ---------------------------------------------------------------------------
extern "C" void kernel_launch(void* const* d_in, const int* in_sizes, int n_in,
                              void* d_out, int out_size) {
    const float* x     = (const float*)d_in[0];
    const int*   ei    = (const int*)d_in[2];
    const float* W1    = (const float*)d_in[3];
    const float* b1    = (const float*)d_in[4];
    const float* gamma = (const float*)d_in[5];
    const float* beta  = (const float*)d_in[6];
    const float* W2    = (const float*)d_in[7];
    const float* b2    = (const float*)d_in[8];
    float*       out   = (float*)d_out;

    // 1: fused MLP + LayerNorm (also zeroes g_deg)
    mlp_ln_kernel<<<592, 128>>>(x, W1, b1, gamma, beta);

    // 2-6: CSR-by-dst build
    hist_kernel<<<(E_EDGES + 255) / 256, 256>>>(ei);
    scan1_kernel<<<49, 1024>>>();
    scan2_kernel<<<1, 64>>>();
    scan3_kernel<<<(N_NODES + 255) / 256, 256>>>();
    fill_kernel<<<(E_EDGES + 255) / 256, 256>>>(ei);

    // 7: fused gather-min + output GEMM
    gather_out_kernel<<<592, 256>>>(W2, b2, out);
}

// round 8
// speedup vs baseline: 1.9305x; 1.0045x over previous
#include <cuda_runtime.h>

#define N_NODES 50000
#define E_EDGES 1600000
#define IN_C    128
#define HID     64
#define OUT_C   64
#define EPS     1e-5f
#define NEG_SLOPE 0.01f

// Scratch (allocation-free rule: __device__ globals)
__device__ float g_h[N_NODES * HID];     // 12.8 MB  LayerNorm output
__device__ int   g_srcs[E_EDGES];        // 6.4 MB   CSR src lists (by dst)
__device__ int   g_deg[N_NODES];
__device__ int   g_off[N_NODES];
__device__ int   g_cur[N_NODES];
__device__ int   g_counter;

// ---------------------------------------------------------------------------
// Kernel 1: h = LayerNorm(LeakyReLU(x @ W1^T + b1)); also zeroes g_deg+counter.
// 4 rows per warp; W1 as float4 [k/4][j] (LDS.128, conflict-free); x rows in
// warp-private shared read back as broadcast float4. FFMA-bound.
// ---------------------------------------------------------------------------
#define MLP_WARPS 4
__global__ void mlp_ln_kernel(const float* __restrict__ x,
                              const float* __restrict__ W1,
                              const float* __restrict__ b1,
                              const float* __restrict__ gamma,
                              const float* __restrict__ beta) {
    __shared__ float4 sW4[32 * 64];               // 32 KB: [kc][j]
    __shared__ float4 sX4[MLP_WARPS][4][32];      //  8 KB: warp-private x rows
    __shared__ float  sb[HID], sg[HID], sbt[HID];

    for (int idx = threadIdx.x; idx < HID * IN_C; idx += blockDim.x) {
        int j = idx / IN_C, k = idx % IN_C;
        ((float*)sW4)[(k >> 2) * 256 + j * 4 + (k & 3)] = W1[idx];
    }
    if (threadIdx.x < HID) {
        sb[threadIdx.x]  = b1[threadIdx.x];
        sg[threadIdx.x]  = gamma[threadIdx.x];
        sbt[threadIdx.x] = beta[threadIdx.x];
    }
    // reset histogram + offset counter for this launch
    int gt = blockIdx.x * blockDim.x + threadIdx.x;
    if (gt < N_NODES) g_deg[gt] = 0;
    if (gt == 0) g_counter = 0;
    __syncthreads();

    const int warp = threadIdx.x >> 5, lane = threadIdx.x & 31;
    const int NTILES = N_NODES / 4;   // 12500, exact

    for (int tile = blockIdx.x * MLP_WARPS + warp; tile < NTILES;
         tile += gridDim.x * MLP_WARPS) {
        const int row = tile * 4;
        float* sX = (float*)sX4[warp];
        #pragma unroll
        for (int r = 0; r < 4; r++) {
            const float* xr = x + (size_t)(row + r) * IN_C;
            sX[r * IN_C + lane]      = xr[lane];
            sX[r * IN_C + lane + 32] = xr[lane + 32];
            sX[r * IN_C + lane + 64] = xr[lane + 64];
            sX[r * IN_C + lane + 96] = xr[lane + 96];
        }
        __syncwarp();

        float acc0[4], acc1[4];
        #pragma unroll
        for (int r = 0; r < 4; r++) { acc0[r] = sb[lane]; acc1[r] = sb[lane + 32]; }

        #pragma unroll
        for (int kc = 0; kc < 32; kc++) {
            float4 w0 = sW4[kc * 64 + lane];
            float4 w1 = sW4[kc * 64 + lane + 32];
            #pragma unroll
            for (int r = 0; r < 4; r++) {
                float4 a = sX4[warp][r][kc];
                acc0[r] += a.x * w0.x + a.y * w0.y + a.z * w0.z + a.w * w0.w;
                acc1[r] += a.x * w1.x + a.y * w1.y + a.z * w1.z + a.w * w1.w;
            }
        }
        __syncwarp();   // before next tile overwrites sX

        #pragma unroll
        for (int r = 0; r < 4; r++) {
            float a0 = acc0[r], a1 = acc1[r];
            a0 = a0 > 0.f ? a0 : a0 * NEG_SLOPE;
            a1 = a1 > 0.f ? a1 : a1 * NEG_SLOPE;
            float s  = a0 + a1;
            float s2 = a0 * a0 + a1 * a1;
            #pragma unroll
            for (int off = 16; off > 0; off >>= 1) {
                s  += __shfl_xor_sync(0xffffffffu, s,  off);
                s2 += __shfl_xor_sync(0xffffffffu, s2, off);
            }
            float mu   = s * (1.f / HID);
            float var  = s2 * (1.f / HID) - mu * mu;
            float rstd = rsqrtf(var + EPS);

            float* hr = g_h + (size_t)(row + r) * HID;
            hr[lane]      = (a0 - mu) * rstd * sg[lane]      + sbt[lane];
            hr[lane + 32] = (a1 - mu) * rstd * sg[lane + 32] + sbt[lane + 32];
        }
    }
}

// ---------------------------------------------------------------------------
// Kernel 2: degree histogram
// ---------------------------------------------------------------------------
__global__ void hist_kernel(const int* __restrict__ ei) {
    int e = blockIdx.x * blockDim.x + threadIdx.x;
    if (e < E_EDGES) atomicAdd(&g_deg[ei[E_EDGES + e]], 1);
}

// ---------------------------------------------------------------------------
// Kernel 3: range assignment WITHOUT a global prefix scan.
// Bucket order in g_srcs is irrelevant (min is order-independent), so each
// warp scans its 32 degrees and grabs a disjoint range via one atomicAdd.
// Replaces scan1+scan2+scan3. Output remains bitwise deterministic.
// ---------------------------------------------------------------------------
__global__ void offsets_kernel() {
    int i = blockIdx.x * blockDim.x + threadIdx.x;
    int lane = threadIdx.x & 31;
    int deg = (i < N_NODES) ? g_deg[i] : 0;

    // warp-inclusive scan of deg
    int pfx = deg;
    #pragma unroll
    for (int off = 1; off < 32; off <<= 1) {
        int t = __shfl_up_sync(0xffffffffu, pfx, off);
        if (lane >= off) pfx += t;
    }
    int total = __shfl_sync(0xffffffffu, pfx, 31);
    int base = 0;
    if (lane == 31) base = atomicAdd(&g_counter, total);
    base = __shfl_sync(0xffffffffu, base, 31);

    if (i < N_NODES) {
        int o = base + pfx - deg;   // exclusive within warp
        g_off[i] = o;
        g_cur[i] = o;
    }
}

// ---------------------------------------------------------------------------
// Kernel 4: bucket fill
// ---------------------------------------------------------------------------
__global__ void fill_kernel(const int* __restrict__ ei) {
    int e = blockIdx.x * blockDim.x + threadIdx.x;
    if (e < E_EDGES) {
        int src = ei[e];
        int dst = ei[E_EDGES + e];
        int p = atomicAdd(&g_cur[dst], 1);
        g_srcs[p] = src;   // order nondeterministic; min is order-independent
    }
}

// ---------------------------------------------------------------------------
// Kernel 5: fused gather-min + output GEMM.
// One warp per dst. Each lane owns channels (2*lane, 2*lane+1): ONE LDG.64
// per edge, j-loop unrolled x2 with independent min accumulators (breaks the
// fmin dependency chain). Then out[dst] = agg @ W2^T + b2 via float4 shared.
// ---------------------------------------------------------------------------
#define GO_WARPS 8
__global__ void gather_out_kernel(const float* __restrict__ W2,
                                  const float* __restrict__ b2,
                                  float* __restrict__ out) {
    __shared__ float4 sW4[16 * 64];          // 16 KB: [kc][j]
    __shared__ float2 sA2[GO_WARPS][32];     //  2 KB: warp-private agg row
    __shared__ float  sb[OUT_C];

    for (int idx = threadIdx.x; idx < OUT_C * HID; idx += blockDim.x) {
        int j = idx / HID, k = idx % HID;
        ((float*)sW4)[(k >> 2) * 256 + j * 4 + (k & 3)] = W2[idx];
    }
    if (threadIdx.x < OUT_C) sb[threadIdx.x] = b2[threadIdx.x];
    __syncthreads();

    const int warp = threadIdx.x >> 5, lane = threadIdx.x & 31;
    const float inf = __int_as_float(0x7f800000);

    for (int dst = blockIdx.x * GO_WARPS + warp; dst < N_NODES;
         dst += gridDim.x * GO_WARPS) {
        const int start = g_off[dst];
        const int deg   = g_deg[dst];

        float2 ma = make_float2(inf, inf);
        float2 mb = make_float2(inf, inf);

        for (int base = 0; base < deg; base += 32) {
            int cnt = min(32, deg - base);
            int sid = (lane < cnt) ? g_srcs[start + base + lane] : 0;
            int j = 0;
            for (; j + 1 < cnt; j += 2) {
                int s0 = __shfl_sync(0xffffffffu, sid, j);
                int s1 = __shfl_sync(0xffffffffu, sid, j + 1);
                float2 v0 = reinterpret_cast<const float2*>(g_h + (size_t)s0 * HID)[lane];
                float2 v1 = reinterpret_cast<const float2*>(g_h + (size_t)s1 * HID)[lane];
                ma.x = fminf(ma.x, v0.x); ma.y = fminf(ma.y, v0.y);
                mb.x = fminf(mb.x, v1.x); mb.y = fminf(mb.y, v1.y);
            }
            if (j < cnt) {
                int s0 = __shfl_sync(0xffffffffu, sid, j);
                float2 v0 = reinterpret_cast<const float2*>(g_h + (size_t)s0 * HID)[lane];
                ma.x = fminf(ma.x, v0.x); ma.y = fminf(ma.y, v0.y);
            }
        }
        float2 m = make_float2(fminf(ma.x, mb.x), fminf(ma.y, mb.y));
        if (deg == 0) { m.x = 0.f; m.y = 0.f; }   // PyG fill for isolated nodes

        sA2[warp][lane] = m;                      // STS.64, conflict-free
        __syncwarp();

        float acc0 = sb[lane], acc1 = sb[lane + 32];
        const float4* sA4 = reinterpret_cast<const float4*>(sA2[warp]);
        #pragma unroll
        for (int kc = 0; kc < 16; kc++) {
            float4 a  = sA4[kc];
            float4 w0 = sW4[kc * 64 + lane];
            float4 w1 = sW4[kc * 64 + lane + 32];
            acc0 += a.x * w0.x + a.y * w0.y + a.z * w0.z + a.w * w0.w;
            acc1 += a.x * w1.x + a.y * w1.y + a.z * w1.z + a.w * w1.w;
        }
        __syncwarp();

        float* orow = out + (size_t)dst * OUT_C;
        orow[lane]      = acc0;
        orow[lane + 32] = acc1;
    }
}

// ---------------------------------------------------------------------------
// Launch
// Inputs: 0:x 1:x_e 2:edge_index(int32) 3:W1 4:b1 5:gamma 6:beta 7:W2 8:b2
// ---------------------------------------------------------------------------
extern "C" void kernel_launch(void* const* d_in, const int* in_sizes, int n_in,
                              void* d_out, int out_size) {
    const float* x     = (const float*)d_in[0];
    const int*   ei    = (const int*)d_in[2];
    const float* W1    = (const float*)d_in[3];
    const float* b1    = (const float*)d_in[4];
    const float* gamma = (const float*)d_in[5];
    const float* beta  = (const float*)d_in[6];
    const float* W2    = (const float*)d_in[7];
    const float* b2    = (const float*)d_in[8];
    float*       out   = (float*)d_out;

    // 1: fused MLP + LayerNorm (also resets g_deg / g_counter)
    mlp_ln_kernel<<<592, 128>>>(x, W1, b1, gamma, beta);

    // 2-4: CSR-by-dst build (no prefix scan)
    hist_kernel<<<(E_EDGES + 255) / 256, 256>>>(ei);
    offsets_kernel<<<(N_NODES + 255) / 256, 256>>>();
    fill_kernel<<<(E_EDGES + 255) / 256, 256>>>(ei);

    // 5: fused gather-min + output GEMM
    gather_out_kernel<<<592, 256>>>(W2, b2, out);
}

// round 9
// speedup vs baseline: 2.1033x; 1.0895x over previous
#include <cuda_runtime.h>
#include <cuda_fp16.h>

#define N_NODES 50000
#define E_EDGES 1600000
#define IN_C    128
#define HID     64
#define OUT_C   64
#define EPS     1e-5f
#define NEG_SLOPE 0.01f

// Scratch (allocation-free rule: __device__ globals).
// Cross-launch invariant: g_deg == 0 and g_counter == 0 at kernel_launch entry
// (BSS-zero on first call; gather_out_kernel re-zeroes them every launch).
__device__ __half2 g_h2[N_NODES * 32];   // 6.4 MB  LN output, lane l owns ch (l, l+32)
__device__ int     g_srcs[E_EDGES];      // 6.4 MB  CSR src lists (by dst)
__device__ int     g_deg[N_NODES];
__device__ int     g_off[N_NODES];
__device__ int     g_cur[N_NODES];
__device__ int     g_counter;

// ---------------------------------------------------------------------------
// Kernel 1: h = LayerNorm(LeakyReLU(x @ W1^T + b1)) stored as half2,
// PLUS the dst-degree histogram (fire-and-forget REDG, overlaps FFMA work).
// 4 rows per warp; W1 as float4 [k/4][j]; x rows staged in warp-private shared.
// ---------------------------------------------------------------------------
#define MLP_WARPS 4
__global__ void mlp_ln_kernel(const float* __restrict__ x,
                              const int*   __restrict__ ei,
                              const float* __restrict__ W1,
                              const float* __restrict__ b1,
                              const float* __restrict__ gamma,
                              const float* __restrict__ beta) {
    __shared__ float4 sW4[32 * 64];               // 32 KB: [kc][j]
    __shared__ float4 sX4[MLP_WARPS][4][32];      //  8 KB: warp-private x rows
    __shared__ float  sb[HID], sg[HID], sbt[HID];

    // Histogram of dst degrees (deg pre-zeroed by previous launch's gather).
    // REDG no-return atomics: issue and move on; FFMA below hides them.
    {
        const int4* dsts = reinterpret_cast<const int4*>(ei + E_EDGES);
        for (int c = blockIdx.x * blockDim.x + threadIdx.x; c < E_EDGES / 4;
             c += gridDim.x * blockDim.x) {
            int4 d = dsts[c];
            atomicAdd(&g_deg[d.x], 1);
            atomicAdd(&g_deg[d.y], 1);
            atomicAdd(&g_deg[d.z], 1);
            atomicAdd(&g_deg[d.w], 1);
        }
    }

    for (int idx = threadIdx.x; idx < HID * IN_C; idx += blockDim.x) {
        int j = idx / IN_C, k = idx % IN_C;
        ((float*)sW4)[(k >> 2) * 256 + j * 4 + (k & 3)] = W1[idx];
    }
    if (threadIdx.x < HID) {
        sb[threadIdx.x]  = b1[threadIdx.x];
        sg[threadIdx.x]  = gamma[threadIdx.x];
        sbt[threadIdx.x] = beta[threadIdx.x];
    }
    __syncthreads();

    const int warp = threadIdx.x >> 5, lane = threadIdx.x & 31;
    const int NTILES = N_NODES / 4;   // 12500, exact

    for (int tile = blockIdx.x * MLP_WARPS + warp; tile < NTILES;
         tile += gridDim.x * MLP_WARPS) {
        const int row = tile * 4;
        float* sX = (float*)sX4[warp];
        #pragma unroll
        for (int r = 0; r < 4; r++) {
            const float* xr = x + (size_t)(row + r) * IN_C;
            sX[r * IN_C + lane]      = xr[lane];
            sX[r * IN_C + lane + 32] = xr[lane + 32];
            sX[r * IN_C + lane + 64] = xr[lane + 64];
            sX[r * IN_C + lane + 96] = xr[lane + 96];
        }
        __syncwarp();

        float acc0[4], acc1[4];
        #pragma unroll
        for (int r = 0; r < 4; r++) { acc0[r] = sb[lane]; acc1[r] = sb[lane + 32]; }

        #pragma unroll
        for (int kc = 0; kc < 32; kc++) {
            float4 w0 = sW4[kc * 64 + lane];
            float4 w1 = sW4[kc * 64 + lane + 32];
            #pragma unroll
            for (int r = 0; r < 4; r++) {
                float4 a = sX4[warp][r][kc];
                acc0[r] += a.x * w0.x + a.y * w0.y + a.z * w0.z + a.w * w0.w;
                acc1[r] += a.x * w1.x + a.y * w1.y + a.z * w1.z + a.w * w1.w;
            }
        }
        __syncwarp();   // before next tile overwrites sX

        #pragma unroll
        for (int r = 0; r < 4; r++) {
            float a0 = acc0[r], a1 = acc1[r];
            a0 = a0 > 0.f ? a0 : a0 * NEG_SLOPE;
            a1 = a1 > 0.f ? a1 : a1 * NEG_SLOPE;
            float s  = a0 + a1;
            float s2 = a0 * a0 + a1 * a1;
            #pragma unroll
            for (int off = 16; off > 0; off >>= 1) {
                s  += __shfl_xor_sync(0xffffffffu, s,  off);
                s2 += __shfl_xor_sync(0xffffffffu, s2, off);
            }
            float mu   = s * (1.f / HID);
            float var  = s2 * (1.f / HID) - mu * mu;
            float rstd = rsqrtf(var + EPS);

            float n0 = (a0 - mu) * rstd * sg[lane]      + sbt[lane];
            float n1 = (a1 - mu) * rstd * sg[lane + 32] + sbt[lane + 32];
            g_h2[(size_t)(row + r) * 32 + lane] = __floats2half2_rn(n0, n1);
        }
    }
}

// ---------------------------------------------------------------------------
// Kernel 2: range assignment without a global prefix scan.
// Bucket order is irrelevant (min is order-independent): warp-scan the 32
// degrees, grab a disjoint range with one atomicAdd. g_counter pre-zeroed.
// ---------------------------------------------------------------------------
__global__ void offsets_kernel() {
    int i = blockIdx.x * blockDim.x + threadIdx.x;
    int lane = threadIdx.x & 31;
    int deg = (i < N_NODES) ? g_deg[i] : 0;

    int pfx = deg;
    #pragma unroll
    for (int off = 1; off < 32; off <<= 1) {
        int t = __shfl_up_sync(0xffffffffu, pfx, off);
        if (lane >= off) pfx += t;
    }
    int total = __shfl_sync(0xffffffffu, pfx, 31);
    int base = 0;
    if (lane == 31) base = atomicAdd(&g_counter, total);
    base = __shfl_sync(0xffffffffu, base, 31);

    if (i < N_NODES) {
        int o = base + pfx - deg;
        g_off[i] = o;
        g_cur[i] = o;
    }
}

// ---------------------------------------------------------------------------
// Kernel 3: bucket fill, 4 edges per thread (int4 loads, 4 independent
// ATOMG chains in flight -> 318-cyc latency amortized 4x).
// ---------------------------------------------------------------------------
__global__ void fill_kernel(const int* __restrict__ ei) {
    int t = blockIdx.x * blockDim.x + threadIdx.x;
    if (t >= E_EDGES / 4) return;
    int4 s = reinterpret_cast<const int4*>(ei)[t];
    int4 d = reinterpret_cast<const int4*>(ei + E_EDGES)[t];
    int p0 = atomicAdd(&g_cur[d.x], 1);
    int p1 = atomicAdd(&g_cur[d.y], 1);
    int p2 = atomicAdd(&g_cur[d.z], 1);
    int p3 = atomicAdd(&g_cur[d.w], 1);
    g_srcs[p0] = s.x;
    g_srcs[p1] = s.y;
    g_srcs[p2] = s.z;
    g_srcs[p3] = s.w;   // bucket order nondeterministic; min is order-independent
}

// ---------------------------------------------------------------------------
// Kernel 4: fused gather-min + output GEMM.
// One warp per dst. One LDG.32 (half2) + HMNMX2 per edge-lane; 4 independent
// accumulators. Also re-zeroes g_deg / g_counter for the next launch.
// ---------------------------------------------------------------------------
#define GO_WARPS 8
__global__ void gather_out_kernel(const float* __restrict__ W2,
                                  const float* __restrict__ b2,
                                  float* __restrict__ out) {
    __shared__ float4 sW4[16 * 64];          // 16 KB: [kc][j]
    __shared__ float  sA[GO_WARPS][HID];     //  2 KB: warp-private agg row
    __shared__ float  sb[OUT_C];

    for (int idx = threadIdx.x; idx < OUT_C * HID; idx += blockDim.x) {
        int j = idx / HID, k = idx % HID;
        ((float*)sW4)[(k >> 2) * 256 + j * 4 + (k & 3)] = W2[idx];
    }
    if (threadIdx.x < OUT_C) sb[threadIdx.x] = b2[threadIdx.x];
    if (blockIdx.x == 0 && threadIdx.x == 0) g_counter = 0;  // reset for next launch
    __syncthreads();

    const int warp = threadIdx.x >> 5, lane = threadIdx.x & 31;
    const __half2 hinf = __floats2half2_rn(6.5e4f, 6.5e4f);  // > any LN output

    for (int dst = blockIdx.x * GO_WARPS + warp; dst < N_NODES;
         dst += gridDim.x * GO_WARPS) {
        const int start = g_off[dst];
        const int deg   = g_deg[dst];

        __half2 m0 = hinf, m1 = hinf, m2 = hinf, m3 = hinf;

        for (int base = 0; base < deg; base += 32) {
            int cnt = min(32, deg - base);
            int sid = (lane < cnt) ? g_srcs[start + base + lane] : 0;
            int j = 0;
            for (; j + 3 < cnt; j += 4) {
                int s0 = __shfl_sync(0xffffffffu, sid, j);
                int s1 = __shfl_sync(0xffffffffu, sid, j + 1);
                int s2 = __shfl_sync(0xffffffffu, sid, j + 2);
                int s3 = __shfl_sync(0xffffffffu, sid, j + 3);
                __half2 v0 = g_h2[(size_t)s0 * 32 + lane];
                __half2 v1 = g_h2[(size_t)s1 * 32 + lane];
                __half2 v2 = g_h2[(size_t)s2 * 32 + lane];
                __half2 v3 = g_h2[(size_t)s3 * 32 + lane];
                m0 = __hmin2(m0, v0);
                m1 = __hmin2(m1, v1);
                m2 = __hmin2(m2, v2);
                m3 = __hmin2(m3, v3);
            }
            for (; j < cnt; j++) {
                int s0 = __shfl_sync(0xffffffffu, sid, j);
                m0 = __hmin2(m0, g_h2[(size_t)s0 * 32 + lane]);
            }
        }
        __half2 mh = __hmin2(__hmin2(m0, m1), __hmin2(m2, m3));
        float2 m = __half22float2(mh);
        if (deg == 0) { m.x = 0.f; m.y = 0.f; }   // PyG fill for isolated nodes

        sA[warp][lane]      = m.x;   // ch lane
        sA[warp][lane + 32] = m.y;   // ch lane+32
        if (lane == 0) g_deg[dst] = 0;            // reset for next launch
        __syncwarp();

        float acc0 = sb[lane], acc1 = sb[lane + 32];
        const float4* sA4 = reinterpret_cast<const float4*>(sA[warp]);
        #pragma unroll
        for (int kc = 0; kc < 16; kc++) {
            float4 a  = sA4[kc];
            float4 w0 = sW4[kc * 64 + lane];
            float4 w1 = sW4[kc * 64 + lane + 32];
            acc0 += a.x * w0.x + a.y * w0.y + a.z * w0.z + a.w * w0.w;
            acc1 += a.x * w1.x + a.y * w1.y + a.z * w1.z + a.w * w1.w;
        }
        __syncwarp();

        float* orow = out + (size_t)dst * OUT_C;
        orow[lane]      = acc0;
        orow[lane + 32] = acc1;
    }
}

// ---------------------------------------------------------------------------
// Launch
// Inputs: 0:x 1:x_e 2:edge_index(int32) 3:W1 4:b1 5:gamma 6:beta 7:W2 8:b2
// ---------------------------------------------------------------------------
extern "C" void kernel_launch(void* const* d_in, const int* in_sizes, int n_in,
                              void* d_out, int out_size) {
    const float* x     = (const float*)d_in[0];
    const int*   ei    = (const int*)d_in[2];
    const float* W1    = (const float*)d_in[3];
    const float* b1    = (const float*)d_in[4];
    const float* gamma = (const float*)d_in[5];
    const float* beta  = (const float*)d_in[6];
    const float* W2    = (const float*)d_in[7];
    const float* b2    = (const float*)d_in[8];
    float*       out   = (float*)d_out;

    // 1: fused MLP + LayerNorm + dst-degree histogram
    mlp_ln_kernel<<<592, 128>>>(x, ei, W1, b1, gamma, beta);

    // 2-3: CSR-by-dst build
    offsets_kernel<<<(N_NODES + 255) / 256, 256>>>();
    fill_kernel<<<(E_EDGES / 4 + 255) / 256, 256>>>(ei);

    // 4: fused gather-min + output GEMM (resets g_deg / g_counter)
    gather_out_kernel<<<592, 256>>>(W2, b2, out);
}

// round 10
// speedup vs baseline: 2.2338x; 1.0620x over previous
#include <cuda_runtime.h>
#include <cuda_fp16.h>

#define N_NODES 50000
#define E_EDGES 1600000
#define IN_C    128
#define HID     64
#define OUT_C   64
#define EPS     1e-5f
#define NEG_SLOPE 0.01f

// Scratch (allocation-free rule: __device__ globals).
// Cross-launch invariant: g_deg == 0 and g_counter == 0 at kernel_launch entry
// (BSS-zero on first call; gather_out_kernel re-zeroes them every launch).
__device__ __half2 g_h2[N_NODES * 32];   // 6.4 MB  LN output, lane l owns ch (l, l+32)
__device__ int     g_srcs[E_EDGES];      // 6.4 MB  CSR lists (by dst), BYTE offsets src*128
__device__ int     g_deg[N_NODES];
__device__ int     g_off[N_NODES];
__device__ int     g_cur[N_NODES];
__device__ int     g_counter;

// ---------------------------------------------------------------------------
// Kernel 1: h = LayerNorm(LeakyReLU(x @ W1^T + b1)) stored as half2,
// PLUS the dst-degree histogram (fire-and-forget REDG, overlaps FFMA work).
// ---------------------------------------------------------------------------
#define MLP_WARPS 4
__global__ void mlp_ln_kernel(const float* __restrict__ x,
                              const int*   __restrict__ ei,
                              const float* __restrict__ W1,
                              const float* __restrict__ b1,
                              const float* __restrict__ gamma,
                              const float* __restrict__ beta) {
    __shared__ float4 sW4[32 * 64];               // 32 KB: [kc][j]
    __shared__ float4 sX4[MLP_WARPS][4][32];      //  8 KB: warp-private x rows
    __shared__ float  sb[HID], sg[HID], sbt[HID];

    // Histogram of dst degrees (deg pre-zeroed by previous launch's gather).
    {
        const int4* dsts = reinterpret_cast<const int4*>(ei + E_EDGES);
        for (int c = blockIdx.x * blockDim.x + threadIdx.x; c < E_EDGES / 4;
             c += gridDim.x * blockDim.x) {
            int4 d = dsts[c];
            atomicAdd(&g_deg[d.x], 1);
            atomicAdd(&g_deg[d.y], 1);
            atomicAdd(&g_deg[d.z], 1);
            atomicAdd(&g_deg[d.w], 1);
        }
    }

    for (int idx = threadIdx.x; idx < HID * IN_C; idx += blockDim.x) {
        int j = idx / IN_C, k = idx % IN_C;
        ((float*)sW4)[(k >> 2) * 256 + j * 4 + (k & 3)] = W1[idx];
    }
    if (threadIdx.x < HID) {
        sb[threadIdx.x]  = b1[threadIdx.x];
        sg[threadIdx.x]  = gamma[threadIdx.x];
        sbt[threadIdx.x] = beta[threadIdx.x];
    }
    __syncthreads();

    const int warp = threadIdx.x >> 5, lane = threadIdx.x & 31;
    const int NTILES = N_NODES / 4;   // 12500, exact

    for (int tile = blockIdx.x * MLP_WARPS + warp; tile < NTILES;
         tile += gridDim.x * MLP_WARPS) {
        const int row = tile * 4;
        float* sX = (float*)sX4[warp];
        #pragma unroll
        for (int r = 0; r < 4; r++) {
            const float* xr = x + (size_t)(row + r) * IN_C;
            sX[r * IN_C + lane]      = xr[lane];
            sX[r * IN_C + lane + 32] = xr[lane + 32];
            sX[r * IN_C + lane + 64] = xr[lane + 64];
            sX[r * IN_C + lane + 96] = xr[lane + 96];
        }
        __syncwarp();

        float acc0[4], acc1[4];
        #pragma unroll
        for (int r = 0; r < 4; r++) { acc0[r] = sb[lane]; acc1[r] = sb[lane + 32]; }

        #pragma unroll
        for (int kc = 0; kc < 32; kc++) {
            float4 w0 = sW4[kc * 64 + lane];
            float4 w1 = sW4[kc * 64 + lane + 32];
            #pragma unroll
            for (int r = 0; r < 4; r++) {
                float4 a = sX4[warp][r][kc];
                acc0[r] += a.x * w0.x + a.y * w0.y + a.z * w0.z + a.w * w0.w;
                acc1[r] += a.x * w1.x + a.y * w1.y + a.z * w1.z + a.w * w1.w;
            }
        }
        __syncwarp();   // before next tile overwrites sX

        #pragma unroll
        for (int r = 0; r < 4; r++) {
            float a0 = acc0[r], a1 = acc1[r];
            a0 = a0 > 0.f ? a0 : a0 * NEG_SLOPE;
            a1 = a1 > 0.f ? a1 : a1 * NEG_SLOPE;
            float s  = a0 + a1;
            float s2 = a0 * a0 + a1 * a1;
            #pragma unroll
            for (int off = 16; off > 0; off >>= 1) {
                s  += __shfl_xor_sync(0xffffffffu, s,  off);
                s2 += __shfl_xor_sync(0xffffffffu, s2, off);
            }
            float mu   = s * (1.f / HID);
            float var  = s2 * (1.f / HID) - mu * mu;
            float rstd = rsqrtf(var + EPS);

            float n0 = (a0 - mu) * rstd * sg[lane]      + sbt[lane];
            float n1 = (a1 - mu) * rstd * sg[lane + 32] + sbt[lane + 32];
            g_h2[(size_t)(row + r) * 32 + lane] = __floats2half2_rn(n0, n1);
        }
    }
}

// ---------------------------------------------------------------------------
// Kernel 2: range assignment without a global prefix scan.
// ---------------------------------------------------------------------------
__global__ void offsets_kernel() {
    int i = blockIdx.x * blockDim.x + threadIdx.x;
    int lane = threadIdx.x & 31;
    int deg = (i < N_NODES) ? g_deg[i] : 0;

    int pfx = deg;
    #pragma unroll
    for (int off = 1; off < 32; off <<= 1) {
        int t = __shfl_up_sync(0xffffffffu, pfx, off);
        if (lane >= off) pfx += t;
    }
    int total = __shfl_sync(0xffffffffu, pfx, 31);
    int base = 0;
    if (lane == 31) base = atomicAdd(&g_counter, total);
    base = __shfl_sync(0xffffffffu, base, 31);

    if (i < N_NODES) {
        int o = base + pfx - deg;
        g_off[i] = o;
        g_cur[i] = o;
    }
}

// ---------------------------------------------------------------------------
// Kernel 3: bucket fill, 4 edges per thread. Stores BYTE offsets (src*128)
// so the gather needs no per-edge index arithmetic.
// ---------------------------------------------------------------------------
__global__ void fill_kernel(const int* __restrict__ ei) {
    int t = blockIdx.x * blockDim.x + threadIdx.x;
    if (t >= E_EDGES / 4) return;
    int4 s = reinterpret_cast<const int4*>(ei)[t];
    int4 d = reinterpret_cast<const int4*>(ei + E_EDGES)[t];
    int p0 = atomicAdd(&g_cur[d.x], 1);
    int p1 = atomicAdd(&g_cur[d.y], 1);
    int p2 = atomicAdd(&g_cur[d.z], 1);
    int p3 = atomicAdd(&g_cur[d.w], 1);
    g_srcs[p0] = s.x << 7;   // byte offset into g_h2 (row = 128 B)
    g_srcs[p1] = s.y << 7;
    g_srcs[p2] = s.z << 7;
    g_srcs[p3] = s.w << 7;   // bucket order nondeterministic; min is order-independent
}

// ---------------------------------------------------------------------------
// Kernel 4: fused gather-min + output GEMM.
// One warp per dst; 8 lanes per edge, 4 edges in flight per warp-iteration.
// Lane = q*8+p: loads g_srcs[start + 4j + q] (4 distinct addrs, no shfl),
// then LDG.128 of bytes [16p,16p+16) of the src row, 4x HMNMX2.
// Tail: edge id clamped to deg-1 (re-min of a seen edge is idempotent).
// Cross-quarter combine via shfl_xor(8,16) once per dst.
// ---------------------------------------------------------------------------
#define GO_WARPS 8
__global__ void gather_out_kernel(const float* __restrict__ W2,
                                  const float* __restrict__ b2,
                                  float* __restrict__ out) {
    __shared__ float4 sW4[16 * 64];          // 16 KB: [kc][j]
    __shared__ float  sA[GO_WARPS][HID];     //  2 KB: warp-private agg row
    __shared__ float  sb[OUT_C];

    for (int idx = threadIdx.x; idx < OUT_C * HID; idx += blockDim.x) {
        int j = idx / HID, k = idx % HID;
        ((float*)sW4)[(k >> 2) * 256 + j * 4 + (k & 3)] = W2[idx];
    }
    if (threadIdx.x < OUT_C) sb[threadIdx.x] = b2[threadIdx.x];
    if (blockIdx.x == 0 && threadIdx.x == 0) g_counter = 0;  // reset for next launch
    __syncthreads();

    const int warp = threadIdx.x >> 5, lane = threadIdx.x & 31;
    const int q = lane >> 3;          // quarter: which of 4 concurrent edges
    const int p = lane & 7;           // 16-byte chunk within the 128-B row
    const char* hbase = reinterpret_cast<const char*>(g_h2);
    const __half2 hinf = __floats2half2_rn(6.5e4f, 6.5e4f);  // > any LN output

    for (int dst = blockIdx.x * GO_WARPS + warp; dst < N_NODES;
         dst += gridDim.x * GO_WARPS) {
        const int start = g_off[dst];
        const int deg   = g_deg[dst];

        __half2 m0 = hinf, m1 = hinf, m2 = hinf, m3 = hinf;

        const int iters = (deg + 3) >> 2;
        #pragma unroll 2
        for (int j = 0; j < iters; j++) {
            int e   = min(j * 4 + q, deg - 1);
            int off = g_srcs[start + e];                       // byte offset
            int4 v  = *reinterpret_cast<const int4*>(hbase + off + p * 16);
            m0 = __hmin2(m0, *reinterpret_cast<__half2*>(&v.x));
            m1 = __hmin2(m1, *reinterpret_cast<__half2*>(&v.y));
            m2 = __hmin2(m2, *reinterpret_cast<__half2*>(&v.z));
            m3 = __hmin2(m3, *reinterpret_cast<__half2*>(&v.w));
        }
        // combine the 4 quarters (same p -> same channels)
        #pragma unroll
        for (int o = 8; o <= 16; o <<= 1) {
            m0 = __hmin2(m0, __shfl_xor_sync(0xffffffffu, m0, o));
            m1 = __hmin2(m1, __shfl_xor_sync(0xffffffffu, m1, o));
            m2 = __hmin2(m2, __shfl_xor_sync(0xffffffffu, m2, o));
            m3 = __hmin2(m3, __shfl_xor_sync(0xffffffffu, m3, o));
        }

        if (lane < 8) {   // quarter 0 writes the agg row
            float2 f0 = __half22float2(m0), f1 = __half22float2(m1);
            float2 f2 = __half22float2(m2), f3 = __half22float2(m3);
            if (deg == 0) {   // PyG fill for isolated nodes
                f0 = f1 = f2 = f3 = make_float2(0.f, 0.f);
            }
            int c = p * 4;    // half2 chunk c holds channels (c, c+32)
            sA[warp][c]          = f0.x;  sA[warp][c + 32]     = f0.y;
            sA[warp][c + 1]      = f1.x;  sA[warp][c + 33]     = f1.y;
            sA[warp][c + 2]      = f2.x;  sA[warp][c + 34]     = f2.y;
            sA[warp][c + 3]      = f3.x;  sA[warp][c + 35]     = f3.y;
        }
        if (lane == 0) g_deg[dst] = 0;            // reset for next launch
        __syncwarp();

        float acc0 = sb[lane], acc1 = sb[lane + 32];
        const float4* sA4 = reinterpret_cast<const float4*>(sA[warp]);
        #pragma unroll
        for (int kc = 0; kc < 16; kc++) {
            float4 a  = sA4[kc];
            float4 w0 = sW4[kc * 64 + lane];
            float4 w1 = sW4[kc * 64 + lane + 32];
            acc0 += a.x * w0.x + a.y * w0.y + a.z * w0.z + a.w * w0.w;
            acc1 += a.x * w1.x + a.y * w1.y + a.z * w1.z + a.w * w1.w;
        }
        __syncwarp();

        float* orow = out + (size_t)dst * OUT_C;
        orow[lane]      = acc0;
        orow[lane + 32] = acc1;
    }
}

// ---------------------------------------------------------------------------
// Launch
// Inputs: 0:x 1:x_e 2:edge_index(int32) 3:W1 4:b1 5:gamma 6:beta 7:W2 8:b2
// ---------------------------------------------------------------------------
extern "C" void kernel_launch(void* const* d_in, const int* in_sizes, int n_in,
                              void* d_out, int out_size) {
    const float* x     = (const float*)d_in[0];
    const int*   ei    = (const int*)d_in[2];
    const float* W1    = (const float*)d_in[3];
    const float* b1    = (const float*)d_in[4];
    const float* gamma = (const float*)d_in[5];
    const float* beta  = (const float*)d_in[6];
    const float* W2    = (const float*)d_in[7];
    const float* b2    = (const float*)d_in[8];
    float*       out   = (float*)d_out;

    // 1: fused MLP + LayerNorm + dst-degree histogram
    mlp_ln_kernel<<<592, 128>>>(x, ei, W1, b1, gamma, beta);

    // 2-3: CSR-by-dst build
    offsets_kernel<<<(N_NODES + 255) / 256, 256>>>();
    fill_kernel<<<(E_EDGES / 4 + 255) / 256, 256>>>(ei);

    // 4: fused gather-min + output GEMM (resets g_deg / g_counter)
    gather_out_kernel<<<592, 256>>>(W2, b2, out);
}

// round 12
// speedup vs baseline: 2.3289x; 1.0426x over previous
#include <cuda_runtime.h>
#include <cuda_fp16.h>

#define N_NODES 50000
#define E_EDGES 1600000
#define IN_C    128
#define HID     64
#define OUT_C   64
#define EPS     1e-5f
#define NEG_SLOPE 0.01f

// Scratch (allocation-free rule: __device__ globals).
// Cross-launch invariant: g_deg == 0 and g_counter == 0 at kernel_launch entry
// (BSS-zero on first call; gather_out_kernel re-zeroes them every launch).
__device__ __half2 g_h2[N_NODES * 32];   // 6.4 MB  LN output, lane l owns ch (l, l+32)
__device__ int     g_srcs[E_EDGES];      // 6.4 MB  CSR lists (by dst), BYTE offsets src*128
__device__ int     g_deg[N_NODES];
__device__ int     g_off[N_NODES];
__device__ int     g_cur[N_NODES];
__device__ int     g_counter;

// ---------------------------------------------------------------------------
// Kernel 1: h = LayerNorm(LeakyReLU(x @ W1^T + b1)) stored as half2,
// PLUS the dst-degree histogram (fire-and-forget REDG, overlaps FFMA work).
// ---------------------------------------------------------------------------
#define MLP_WARPS 4
__global__ void mlp_ln_kernel(const float* __restrict__ x,
                              const int*   __restrict__ ei,
                              const float* __restrict__ W1,
                              const float* __restrict__ b1,
                              const float* __restrict__ gamma,
                              const float* __restrict__ beta) {
    __shared__ float4 sW4[32 * 64];               // 32 KB: [kc][j]
    __shared__ float4 sX4[MLP_WARPS][4][32];      //  8 KB: warp-private x rows
    __shared__ float  sb[HID], sg[HID], sbt[HID];

    // Histogram of dst degrees (deg pre-zeroed by previous launch's gather).
    {
        const int4* dsts = reinterpret_cast<const int4*>(ei + E_EDGES);
        for (int c = blockIdx.x * blockDim.x + threadIdx.x; c < E_EDGES / 4;
             c += gridDim.x * blockDim.x) {
            int4 d = dsts[c];
            atomicAdd(&g_deg[d.x], 1);
            atomicAdd(&g_deg[d.y], 1);
            atomicAdd(&g_deg[d.z], 1);
            atomicAdd(&g_deg[d.w], 1);
        }
    }

    for (int idx = threadIdx.x; idx < HID * IN_C; idx += blockDim.x) {
        int j = idx / IN_C, k = idx % IN_C;
        ((float*)sW4)[(k >> 2) * 256 + j * 4 + (k & 3)] = W1[idx];
    }
    if (threadIdx.x < HID) {
        sb[threadIdx.x]  = b1[threadIdx.x];
        sg[threadIdx.x]  = gamma[threadIdx.x];
        sbt[threadIdx.x] = beta[threadIdx.x];
    }
    __syncthreads();

    const int warp = threadIdx.x >> 5, lane = threadIdx.x & 31;
    const int NTILES = N_NODES / 4;   // 12500, exact

    for (int tile = blockIdx.x * MLP_WARPS + warp; tile < NTILES;
         tile += gridDim.x * MLP_WARPS) {
        const int row = tile * 4;
        float* sX = (float*)sX4[warp];
        #pragma unroll
        for (int r = 0; r < 4; r++) {
            const float* xr = x + (size_t)(row + r) * IN_C;
            sX[r * IN_C + lane]      = xr[lane];
            sX[r * IN_C + lane + 32] = xr[lane + 32];
            sX[r * IN_C + lane + 64] = xr[lane + 64];
            sX[r * IN_C + lane + 96] = xr[lane + 96];
        }
        __syncwarp();

        float acc0[4], acc1[4];
        #pragma unroll
        for (int r = 0; r < 4; r++) { acc0[r] = sb[lane]; acc1[r] = sb[lane + 32]; }

        #pragma unroll
        for (int kc = 0; kc < 32; kc++) {
            float4 w0 = sW4[kc * 64 + lane];
            float4 w1 = sW4[kc * 64 + lane + 32];
            #pragma unroll
            for (int r = 0; r < 4; r++) {
                float4 a = sX4[warp][r][kc];
                acc0[r] += a.x * w0.x + a.y * w0.y + a.z * w0.z + a.w * w0.w;
                acc1[r] += a.x * w1.x + a.y * w1.y + a.z * w1.z + a.w * w1.w;
            }
        }
        __syncwarp();   // before next tile overwrites sX

        #pragma unroll
        for (int r = 0; r < 4; r++) {
            float a0 = acc0[r], a1 = acc1[r];
            a0 = a0 > 0.f ? a0 : a0 * NEG_SLOPE;
            a1 = a1 > 0.f ? a1 : a1 * NEG_SLOPE;
            float s  = a0 + a1;
            float s2 = a0 * a0 + a1 * a1;
            #pragma unroll
            for (int off = 16; off > 0; off >>= 1) {
                s  += __shfl_xor_sync(0xffffffffu, s,  off);
                s2 += __shfl_xor_sync(0xffffffffu, s2, off);
            }
            float mu   = s * (1.f / HID);
            float var  = s2 * (1.f / HID) - mu * mu;
            float rstd = rsqrtf(var + EPS);

            float n0 = (a0 - mu) * rstd * sg[lane]      + sbt[lane];
            float n1 = (a1 - mu) * rstd * sg[lane + 32] + sbt[lane + 32];
            g_h2[(size_t)(row + r) * 32 + lane] = __floats2half2_rn(n0, n1);
        }
    }
}

// ---------------------------------------------------------------------------
// Kernel 2: range assignment without a global prefix scan.
// ---------------------------------------------------------------------------
__global__ void offsets_kernel() {
    int i = blockIdx.x * blockDim.x + threadIdx.x;
    int lane = threadIdx.x & 31;
    int deg = (i < N_NODES) ? g_deg[i] : 0;

    int pfx = deg;
    #pragma unroll
    for (int off = 1; off < 32; off <<= 1) {
        int t = __shfl_up_sync(0xffffffffu, pfx, off);
        if (lane >= off) pfx += t;
    }
    int total = __shfl_sync(0xffffffffu, pfx, 31);
    int base = 0;
    if (lane == 31) base = atomicAdd(&g_counter, total);
    base = __shfl_sync(0xffffffffu, base, 31);

    if (i < N_NODES) {
        int o = base + pfx - deg;
        g_off[i] = o;
        g_cur[i] = o;
    }
}

// ---------------------------------------------------------------------------
// Kernel 3: bucket fill, 4 edges per thread. Stores BYTE offsets (src*128).
// ---------------------------------------------------------------------------
__global__ void fill_kernel(const int* __restrict__ ei) {
    int t = blockIdx.x * blockDim.x + threadIdx.x;
    if (t >= E_EDGES / 4) return;
    int4 s = reinterpret_cast<const int4*>(ei)[t];
    int4 d = reinterpret_cast<const int4*>(ei + E_EDGES)[t];
    int p0 = atomicAdd(&g_cur[d.x], 1);
    int p1 = atomicAdd(&g_cur[d.y], 1);
    int p2 = atomicAdd(&g_cur[d.z], 1);
    int p3 = atomicAdd(&g_cur[d.w], 1);
    g_srcs[p0] = s.x << 7;   // byte offset into g_h2 (row = 128 B)
    g_srcs[p1] = s.y << 7;
    g_srcs[p2] = s.z << 7;
    g_srcs[p3] = s.w << 7;   // bucket order nondeterministic; min is order-independent
}

// ---------------------------------------------------------------------------
// Kernel 4: fused gather-min + output GEMM, 4 DSTS PER WARP.
// Phase 1 (x4): 8 lanes/edge, 4 edges in flight; agg row -> sA[warp][r].
// Phase 2: one 4-row GEMM — weight LDS.128 amortized over 4 dsts, activation
// rows read as broadcast float4 (conflict-free). Kills the 128-cyc/dst LDS
// crossbar cost that dominated round 10.
// ---------------------------------------------------------------------------
#define GO_WARPS 8
__global__ void gather_out_kernel(const float* __restrict__ W2,
                                  const float* __restrict__ b2,
                                  float* __restrict__ out) {
    __shared__ float4 sW4[16 * 64];             // 16 KB: [kc][j]
    __shared__ float4 sA4[GO_WARPS][4][16];     //  4 KB: 4 agg rows per warp
    __shared__ float  sb[OUT_C];

    for (int idx = threadIdx.x; idx < OUT_C * HID; idx += blockDim.x) {
        int j = idx / HID, k = idx % HID;
        ((float*)sW4)[(k >> 2) * 256 + j * 4 + (k & 3)] = W2[idx];
    }
    if (threadIdx.x < OUT_C) sb[threadIdx.x] = b2[threadIdx.x];
    if (blockIdx.x == 0 && threadIdx.x == 0) g_counter = 0;  // reset for next launch
    __syncthreads();

    const int warp = threadIdx.x >> 5, lane = threadIdx.x & 31;
    const int q = lane >> 3;          // quarter: which of 4 concurrent edges
    const int p = lane & 7;           // 16-byte chunk within the 128-B row
    const char* hbase = reinterpret_cast<const char*>(g_h2);
    const __half2 hinf = __floats2half2_rn(6.5e4f, 6.5e4f);  // > any LN output
    const int NTILES = N_NODES / 4;   // 12500, exact

    for (int tile = blockIdx.x * GO_WARPS + warp; tile < NTILES;
         tile += gridDim.x * GO_WARPS) {
        const int dst0 = tile * 4;

        // ---- Phase 1: gather-min for 4 dsts ----
        #pragma unroll
        for (int r = 0; r < 4; r++) {
            const int dst   = dst0 + r;
            const int start = g_off[dst];
            const int deg   = g_deg[dst];

            __half2 m0 = hinf, m1 = hinf, m2 = hinf, m3 = hinf;
            const int iters = (deg + 3) >> 2;
            #pragma unroll 2
            for (int j = 0; j < iters; j++) {
                int e   = min(j * 4 + q, deg - 1);
                int off = g_srcs[start + e];                       // byte offset
                int4 v  = *reinterpret_cast<const int4*>(hbase + off + p * 16);
                m0 = __hmin2(m0, *reinterpret_cast<__half2*>(&v.x));
                m1 = __hmin2(m1, *reinterpret_cast<__half2*>(&v.y));
                m2 = __hmin2(m2, *reinterpret_cast<__half2*>(&v.z));
                m3 = __hmin2(m3, *reinterpret_cast<__half2*>(&v.w));
            }
            // combine the 4 quarters (same p -> same channels)
            #pragma unroll
            for (int o = 8; o <= 16; o <<= 1) {
                m0 = __hmin2(m0, __shfl_xor_sync(0xffffffffu, m0, o));
                m1 = __hmin2(m1, __shfl_xor_sync(0xffffffffu, m1, o));
                m2 = __hmin2(m2, __shfl_xor_sync(0xffffffffu, m2, o));
                m3 = __hmin2(m3, __shfl_xor_sync(0xffffffffu, m3, o));
            }

            if (lane < 8) {   // quarter 0 writes the agg row
                float2 f0 = __half22float2(m0), f1 = __half22float2(m1);
                float2 f2 = __half22float2(m2), f3 = __half22float2(m3);
                if (deg == 0) {   // PyG fill for isolated nodes
                    f0 = f1 = f2 = f3 = make_float2(0.f, 0.f);
                }
                float* sA = (float*)sA4[warp][r];
                int c = p * 4;    // half2 chunk c holds channels (c, c+32)
                sA[c]      = f0.x;  sA[c + 32] = f0.y;
                sA[c + 1]  = f1.x;  sA[c + 33] = f1.y;
                sA[c + 2]  = f2.x;  sA[c + 34] = f2.y;
                sA[c + 3]  = f3.x;  sA[c + 35] = f3.y;
            }
            if (lane == 0) g_deg[dst] = 0;        // reset for next launch
        }
        __syncwarp();

        // ---- Phase 2: 4-row GEMM, weights amortized ----
        float acc0[4], acc1[4];
        #pragma unroll
        for (int r = 0; r < 4; r++) { acc0[r] = sb[lane]; acc1[r] = sb[lane + 32]; }

        #pragma unroll
        for (int kc = 0; kc < 16; kc++) {
            float4 w0 = sW4[kc * 64 + lane];
            float4 w1 = sW4[kc * 64 + lane + 32];
            #pragma unroll
            for (int r = 0; r < 4; r++) {
                float4 a = sA4[warp][r][kc];      // broadcast, conflict-free
                acc0[r] += a.x * w0.x + a.y * w0.y + a.z * w0.z + a.w * w0.w;
                acc1[r] += a.x * w1.x + a.y * w1.y + a.z * w1.z + a.w * w1.w;
            }
        }
        __syncwarp();   // before next tile overwrites sA4

        #pragma unroll
        for (int r = 0; r < 4; r++) {
            float* orow = out + (size_t)(dst0 + r) * OUT_C;
            orow[lane]      = acc0[r];
            orow[lane + 32] = acc1[r];
        }
    }
}

// ---------------------------------------------------------------------------
// Launch
// Inputs: 0:x 1:x_e 2:edge_index(int32) 3:W1 4:b1 5:gamma 6:beta 7:W2 8:b2
// ---------------------------------------------------------------------------
extern "C" void kernel_launch(void* const* d_in, const int* in_sizes, int n_in,
                              void* d_out, int out_size) {
    const float* x     = (const float*)d_in[0];
    const int*   ei    = (const int*)d_in[2];
    const float* W1    = (const float*)d_in[3];
    const float* b1    = (const float*)d_in[4];
    const float* gamma = (const float*)d_in[5];
    const float* beta  = (const float*)d_in[6];
    const float* W2    = (const float*)d_in[7];
    const float* b2    = (const float*)d_in[8];
    float*       out   = (float*)d_out;

    // 1: fused MLP + LayerNorm + dst-degree histogram
    mlp_ln_kernel<<<592, 128>>>(x, ei, W1, b1, gamma, beta);

    // 2-3: CSR-by-dst build
    offsets_kernel<<<(N_NODES + 255) / 256, 256>>>();
    fill_kernel<<<(E_EDGES / 4 + 255) / 256, 256>>>(ei);

    // 4: fused gather-min + output GEMM (4 dsts/warp; resets g_deg / g_counter)
    gather_out_kernel<<<592, 256>>>(W2, b2, out);
}